// round 10
// baseline (speedup 1.0000x reference)
#include <cuda_runtime.h>
#include <cuda_bf16.h>
#include <math.h>

#define MAXN   100000
#define MAXNP  (MAXN + 64)
#define FDIM   44
#define F2DIM  88
#define K4F    11            // FDIM/4
#define K4F2   22            // F2DIM/4
#define FEATD  1019
#define MAXG   1024
#define MAXE   1000000
#define SCANB  1024
#define MAXNB  ((MAXN + SCANB - 1) / SCANB)

// ---------------- scratch (allocation-free rule: __device__ globals) ----------------
__device__ __align__(256) float g_bufA[MAXNP * F2DIM];
__device__ __align__(256) float g_bufB[MAXNP * F2DIM];
__device__ __align__(256) float g_dinv[MAXN];
__device__ __align__(256) int   g_indeg[MAXN];
__device__ __align__(256) int   g_cursor[MAXN];
__device__ __align__(256) int   g_off[MAXN + 1];
__device__ __align__(256) int2  g_epack[MAXE];          // (src, __float_as_int(norm))
__device__ __align__(256) int   g_partial[MAXNB + 1];
__device__ __align__(256) int   g_bofs[MAXNB + 1];
__device__ __align__(256) float g_pool[MAXG * FDIM];

// ---------------- f32x2 packed math helpers ----------------
__device__ __forceinline__ unsigned long long ffma2(unsigned long long a,
                                                    unsigned long long b,
                                                    unsigned long long c) {
    unsigned long long d;
    asm("fma.rn.f32x2 %0, %1, %2, %3;" : "=l"(d) : "l"(a), "l"(b), "l"(c));
    return d;
}
__device__ __forceinline__ unsigned long long splat2(float x) {
    unsigned long long d;
    asm("mov.b64 %0, {%1, %2};" : "=l"(d) : "r"(__float_as_uint(x)), "r"(__float_as_uint(x)));
    return d;
}
__device__ __forceinline__ unsigned long long pack2(float lo, float hi) {
    unsigned long long d;
    asm("mov.b64 %0, {%1, %2};" : "=l"(d) : "r"(__float_as_uint(lo)), "r"(__float_as_uint(hi)));
    return d;
}

// ---------------- degree count ----------------
__global__ void k_count(const int* __restrict__ dst, int* __restrict__ indeg, int E) {
    int e = blockIdx.x * blockDim.x + threadIdx.x;
    if (e < E) atomicAdd(&indeg[dst[e]], 1);
}

// ---------------- scan phase 1 (+ dinv + cursor zero fused) ----------------
__global__ void k_scan1(const int* __restrict__ indeg, int* __restrict__ off,
                        int* __restrict__ partial, float* __restrict__ dinv,
                        int* __restrict__ cursor, int n) {
    __shared__ int wsum[32];
    int tid = threadIdx.x, lane = tid & 31, wid = tid >> 5;
    int idx = blockIdx.x * SCANB + tid;
    int v = (idx < n) ? indeg[idx] : 0;
    if (idx < n) {
        dinv[idx] = rsqrtf(1.0f + (float)v);
        cursor[idx] = 0;
    }
    int incl = v;
    #pragma unroll
    for (int d = 1; d < 32; d <<= 1) {
        int t = __shfl_up_sync(0xffffffffu, incl, d);
        if (lane >= d) incl += t;
    }
    if (lane == 31) wsum[wid] = incl;
    __syncthreads();
    if (wid == 0) {
        int w = wsum[lane];
        #pragma unroll
        for (int d = 1; d < 32; d <<= 1) {
            int t = __shfl_up_sync(0xffffffffu, w, d);
            if (lane >= d) w += t;
        }
        wsum[lane] = w;
    }
    __syncthreads();
    int warpoff = (wid == 0) ? 0 : wsum[wid - 1];
    if (idx < n) off[idx] = warpoff + incl - v;
    if (tid == 0) partial[blockIdx.x] = wsum[31];
}

// ---------------- scan phase 2 (block offsets) ----------------
__global__ void k_scan2(const int* __restrict__ partial, int* __restrict__ bofs, int nb) {
    __shared__ int wsum[32];
    int tid = threadIdx.x, lane = tid & 31, wid = tid >> 5;  // 128 threads
    int v = (tid < nb) ? partial[tid] : 0;
    int incl = v;
    #pragma unroll
    for (int d = 1; d < 32; d <<= 1) {
        int t = __shfl_up_sync(0xffffffffu, incl, d);
        if (lane >= d) incl += t;
    }
    if (lane == 31) wsum[wid] = incl;
    __syncthreads();
    if (wid == 0 && lane < 4) {
        int w = wsum[lane];
        #pragma unroll
        for (int d = 1; d < 4; d <<= 1) {
            int t = __shfl_up_sync(0x0000000fu, w, d);
            if (lane >= d) w += t;
        }
        wsum[lane] = w;
    }
    __syncthreads();
    int warpoff = (wid == 0) ? 0 : wsum[wid - 1];
    if (tid < nb) bofs[tid] = warpoff + incl - v;
}

// ---------------- CSR fill (applies bofs correction inline) ----------------
__global__ void k_fill(const int* __restrict__ src, const int* __restrict__ dst,
                       const float* __restrict__ dinv, const int* __restrict__ off,
                       const int* __restrict__ bofs,
                       int* __restrict__ cursor, int2* __restrict__ ep, int E) {
    int e = blockIdx.x * blockDim.x + threadIdx.x;
    if (e >= E) return;
    int s = src[e], d = dst[e];
    int base = off[d] + bofs[d >> 10];
    int p = base + atomicAdd(&cursor[d], 1);
    ep[p] = make_int2(s, __float_as_int(dinv[s] * dinv[d]));
}

// ---------------- t = act(h) @ W (+bias), 8 rows x one float4-out-chunk per thread ----------------
// (R4 register-blocked variant — fastest measured mm)
template <int KIN, int KOUT4, int RELU, int BIAS>
__global__ void __launch_bounds__(256) k_mm(const float* __restrict__ h,
                                            const float* __restrict__ W,
                                            const float* __restrict__ bias,
                                            float* __restrict__ t, int n) {
    const int R = 8;
    int gid = blockIdx.x * 256 + threadIdx.x;
    int c4 = gid % KOUT4;
    int rb = gid / KOUT4;
    int row0 = rb * R;
    if (row0 >= n) return;

    const ulonglong2* Wv = (const ulonglong2*)W;
    unsigned long long binit0 = 0ull, binit1 = 0ull;
    if (BIAS) {
        float4 b4 = ((const float4*)bias)[c4];
        binit0 = pack2(b4.x, b4.y);
        binit1 = pack2(b4.z, b4.w);
    }
    unsigned long long acc0[R], acc1[R];
    #pragma unroll
    for (int r = 0; r < R; r++) { acc0[r] = binit0; acc1[r] = binit1; }

    const float4* hp[R];
    #pragma unroll
    for (int r = 0; r < R; r++) {
        int rr = row0 + r; if (rr > n - 1) rr = n - 1;
        hp[r] = (const float4*)(h + (size_t)rr * KIN);
    }

    #pragma unroll 2
    for (int k4 = 0; k4 < KIN / 4; k4++) {
        float4 hv[R];
        #pragma unroll
        for (int r = 0; r < R; r++) {
            float4 v = hp[r][k4];
            if (RELU) {
                v.x = fmaxf(v.x, 0.f); v.y = fmaxf(v.y, 0.f);
                v.z = fmaxf(v.z, 0.f); v.w = fmaxf(v.w, 0.f);
            }
            hv[r] = v;
        }
        #pragma unroll
        for (int kk = 0; kk < 4; kk++) {
            ulonglong2 wv = Wv[(k4 * 4 + kk) * KOUT4 + c4];
            #pragma unroll
            for (int r = 0; r < R; r++) {
                float hs = (kk == 0) ? hv[r].x : (kk == 1) ? hv[r].y
                         : (kk == 2) ? hv[r].z : hv[r].w;
                unsigned long long s = splat2(hs);
                acc0[r] = ffma2(s, wv.x, acc0[r]);
                acc1[r] = ffma2(s, wv.y, acc1[r]);
            }
        }
    }
    #pragma unroll
    for (int r = 0; r < R; r++) {
        int rr = row0 + r;
        if (rr < n) {
            ulonglong2 o; o.x = acc0[r]; o.y = acc1[r];
            ((ulonglong2*)t)[(size_t)rr * KOUT4 + c4] = o;
        }
    }
}

// ---------------- PAIRED F=44 aggregation ----------------
// TWO threads per (node, float4-chunk): thread h in {0,1} accumulates half of the
// node's edge list (contiguous halves, batch-4 MLP gathers), partners combine with
// shfl_xor(1) and h=0 writes. Halves the per-thread serial L2 latency chain.
// POOL=1: h=0 atomicMaxes relu'd result into pool[batch[node]].
template <int RELU, int BIAS, int POOL>
__global__ void __launch_bounds__(256) k_aggr(const float* __restrict__ t,
                                              const int2* __restrict__ ep,
                                              const int* __restrict__ off,
                                              const int* __restrict__ bofs,
                                              const float* __restrict__ dinv,
                                              const float* __restrict__ bias,
                                              float* __restrict__ out,
                                              const int* __restrict__ batch,
                                              float* __restrict__ pool,
                                              int n, int E) {
    int gid = blockIdx.x * 256 + threadIdx.x;
    int pairid = gid >> 1;
    int h = gid & 1;
    int node = pairid / K4F;
    int c4 = pairid - node * K4F;
    if (node >= n) return;          // partner exits too (same node) -> pair stays converged

    const int lane = threadIdx.x & 31;
    const unsigned pmask = 3u << (lane & 30);   // this thread + its pair partner

    const float4* t4 = (const float4*)t;

    float4 acc;
    if (h == 0) {
        // self-loop + bias term only on h=0
        float dd = dinv[node];
        float sl = dd * dd;
        float4 tv = t4[(size_t)node * K4F + c4];
        if (RELU) {
            tv.x = fmaxf(tv.x, 0.f); tv.y = fmaxf(tv.y, 0.f);
            tv.z = fmaxf(tv.z, 0.f); tv.w = fmaxf(tv.w, 0.f);
        }
        if (BIAS) {
            float4 b4 = ((const float4*)bias)[c4];
            acc.x = fmaf(tv.x, sl, b4.x); acc.y = fmaf(tv.y, sl, b4.y);
            acc.z = fmaf(tv.z, sl, b4.z); acc.w = fmaf(tv.w, sl, b4.w);
        } else {
            acc.x = tv.x * sl; acc.y = tv.y * sl;
            acc.z = tv.z * sl; acc.w = tv.w * sl;
        }
    } else {
        acc = make_float4(0.f, 0.f, 0.f, 0.f);
    }

    int beg  = off[node] + bofs[node >> 10];
    int endn = (node == n - 1) ? E : off[node + 1] + bofs[(node + 1) >> 10];
    int deg  = endn - beg;
    int half = (deg + 1) >> 1;
    int j    = beg + h * half;
    int jend = h ? endn : beg + half;

    // batch-4 main loop: independent meta loads then independent gathers
    for (; j + 4 <= jend; j += 4) {
        int2 m[4];
        #pragma unroll
        for (int q = 0; q < 4; q++) m[q] = ep[j + q];
        float4 v[4];
        #pragma unroll
        for (int q = 0; q < 4; q++)
            v[q] = t4[(size_t)m[q].x * K4F + c4];
        #pragma unroll
        for (int q = 0; q < 4; q++) {
            float w = __int_as_float(m[q].y);
            float4 x = v[q];
            if (RELU) {
                x.x = fmaxf(x.x, 0.f); x.y = fmaxf(x.y, 0.f);
                x.z = fmaxf(x.z, 0.f); x.w = fmaxf(x.w, 0.f);
            }
            acc.x = fmaf(x.x, w, acc.x); acc.y = fmaf(x.y, w, acc.y);
            acc.z = fmaf(x.z, w, acc.z); acc.w = fmaf(x.w, w, acc.w);
        }
    }
    // scalar tail (<=3)
    for (; j < jend; j++) {
        int2 m = ep[j];
        float w = __int_as_float(m.y);
        float4 x = t4[(size_t)m.x * K4F + c4];
        if (RELU) {
            x.x = fmaxf(x.x, 0.f); x.y = fmaxf(x.y, 0.f);
            x.z = fmaxf(x.z, 0.f); x.w = fmaxf(x.w, 0.f);
        }
        acc.x = fmaf(x.x, w, acc.x); acc.y = fmaf(x.y, w, acc.y);
        acc.z = fmaf(x.z, w, acc.z); acc.w = fmaf(x.w, w, acc.w);
    }

    // combine pair halves (both lanes execute; pair-converged)
    acc.x += __shfl_xor_sync(pmask, acc.x, 1);
    acc.y += __shfl_xor_sync(pmask, acc.y, 1);
    acc.z += __shfl_xor_sync(pmask, acc.z, 1);
    acc.w += __shfl_xor_sync(pmask, acc.w, 1);

    if (h == 0) {
        if (POOL) {
            int g = batch[node];
            int* pp = (int*)&pool[(size_t)g * FDIM + c4 * 4];
            atomicMax(pp + 0, __float_as_int(fmaxf(acc.x, 0.f)));
            atomicMax(pp + 1, __float_as_int(fmaxf(acc.y, 0.f)));
            atomicMax(pp + 2, __float_as_int(fmaxf(acc.z, 0.f)));
            atomicMax(pp + 3, __float_as_int(fmaxf(acc.w, 0.f)));
        } else {
            ((float4*)out)[(size_t)node * K4F + c4] = acc;
        }
    }
}

// ---------------- final heads: 8 graphs per block ----------------
__global__ void k_final(const float* __restrict__ pool, const float* __restrict__ feat,
                        const float* __restrict__ Wg,  const float* __restrict__ bg,
                        const float* __restrict__ Wf1, const float* __restrict__ bf1,
                        const float* __restrict__ Wf2, const float* __restrict__ bf2,
                        float* __restrict__ out, int G) {
    const int GB = 8;
    int g0 = blockIdx.x * GB;
    int j = threadIdx.x;   // 128
    float acc[GB];
    float bj = bf1[j];
    #pragma unroll
    for (int i = 0; i < GB; i++) acc[i] = bj;
    #pragma unroll 2
    for (int k = 0; k < FEATD; k++) {
        float w = Wf1[k * 128 + j];
        #pragma unroll
        for (int i = 0; i < GB; i++) {
            int g = g0 + i;
            float f = (g < G) ? feat[(size_t)g * FEATD + k] : 0.0f;
            acc[i] = fmaf(f, w, acc[i]);
        }
    }
    float wf2 = Wf2[j];
    __shared__ float red[128];
    __shared__ float sums[GB];
    #pragma unroll
    for (int i = 0; i < GB; i++) {
        red[j] = fmaxf(acc[i], 0.0f) * wf2;
        __syncthreads();
        for (int o = 64; o > 0; o >>= 1) {
            if (j < o) red[j] += red[j + o];
            __syncthreads();
        }
        if (j == 0) sums[i] = red[0];
        __syncthreads();
    }
    if (j < GB) {
        int g = g0 + j;
        if (g < G) {
            float a = bg[0];
            #pragma unroll
            for (int k = 0; k < FDIM; k++)
                a = fmaf(pool[g * FDIM + k], Wg[k], a);
            out[g] = fmaxf(a, 0.0f) + sums[j] + bf2[0];
        }
    }
}

// ----------------------------------------------------------------
extern "C" void kernel_launch(void* const* d_in, const int* in_sizes, int n_in,
                              void* d_out, int out_size) {
    const float* x       = (const float*)d_in[0];
    const int*   ei      = (const int*)  d_in[1];
    const int*   batch   = (const int*)  d_in[2];
    const float* feature = (const float*)d_in[3];
    const float* W1 = (const float*)d_in[4];  const float* b1 = (const float*)d_in[5];
    const float* W2 = (const float*)d_in[6];  const float* b2 = (const float*)d_in[7];
    const float* W3 = (const float*)d_in[8];  const float* b3 = (const float*)d_in[9];
    const float* Wg = (const float*)d_in[10]; const float* bg = (const float*)d_in[11];
    const float* Wf1= (const float*)d_in[12]; const float* bf1= (const float*)d_in[13];
    const float* Wf2= (const float*)d_in[14]; const float* bf2= (const float*)d_in[15];

    const int N = in_sizes[2];
    const int E = in_sizes[1] / 2;
    const int G = in_sizes[3] / FEATD;
    const int NB = (N + SCANB - 1) / SCANB;

    float *A, *B, *dinv, *pool;
    int *indeg, *cursor, *off, *partial, *bofs;
    int2 *ep;
    cudaGetSymbolAddress((void**)&A,      g_bufA);
    cudaGetSymbolAddress((void**)&B,      g_bufB);
    cudaGetSymbolAddress((void**)&dinv,   g_dinv);
    cudaGetSymbolAddress((void**)&indeg,  g_indeg);
    cudaGetSymbolAddress((void**)&cursor, g_cursor);
    cudaGetSymbolAddress((void**)&off,    g_off);
    cudaGetSymbolAddress((void**)&ep,     g_epack);
    cudaGetSymbolAddress((void**)&partial,g_partial);
    cudaGetSymbolAddress((void**)&bofs,   g_bofs);
    cudaGetSymbolAddress((void**)&pool,   g_pool);

    const int* src = ei;
    const int* dst = ei + E;
    float* out = (float*)d_out;

    const int T = 256;
    auto blocks = [&](int work) { return (work + T - 1) / T; };

    // ---- CSR build + norms ----
    cudaMemsetAsync(indeg, 0, N * sizeof(int));
    cudaMemsetAsync(pool, 0, (size_t)G * FDIM * sizeof(float));  // relu identity
    k_count<<<blocks(E), T>>>(dst, indeg, E);
    k_scan1<<<NB, SCANB>>>(indeg, off, partial, dinv, cursor, N);
    k_scan2<<<1, 128>>>(partial, bofs, NB);

    // mm1 is CSR-independent
    {
        int thr = ((N + 7) / 8) * K4F;
        k_mm<FDIM, K4F, 0, 0><<<blocks(thr), T>>>(x, W1, nullptr, A, N);
    }
    k_fill<<<blocks(E), T>>>(src, dst, dinv, off, bofs, cursor, ep, E);

    // B = Agg(A)+b1 ; A = Agg(relu(B)) ; B = A@W2+b2 ; A = relu(B)@W3 ; pool = segmax(relu(Agg(A)+b3))
    k_aggr<0, 1, 0><<<blocks(2 * N * K4F), T>>>(A, ep, off, bofs, dinv, b1, B, nullptr, nullptr, N, E);
    k_aggr<1, 0, 0><<<blocks(2 * N * K4F), T>>>(B, ep, off, bofs, dinv, nullptr, A, nullptr, nullptr, N, E);
    {
        int thr = ((N + 7) / 8) * K4F2;
        k_mm<FDIM, K4F2, 0, 1><<<blocks(thr), T>>>(A, W2, b2, B, N);
    }
    {
        int thr = ((N + 7) / 8) * K4F;
        k_mm<F2DIM, K4F, 1, 0><<<blocks(thr), T>>>(B, W3, nullptr, A, N);
    }
    k_aggr<0, 1, 1><<<blocks(2 * N * K4F), T>>>(A, ep, off, bofs, dinv, b3, nullptr, batch, pool, N, E);

    // ---- heads ----
    k_final<<<(G + 7) / 8, 128>>>(pool, feature, Wg, bg, Wf1, bf1, Wf2, bf2, out, G);
}

// round 12
// speedup vs baseline: 1.5840x; 1.5840x over previous
#include <cuda_runtime.h>
#include <cuda_fp16.h>
#include <cuda_bf16.h>
#include <math.h>

#define MAXN   100000
#define MAXNP  (MAXN + 64)
#define FDIM   44
#define F2DIM  88
#define K4F    11            // FDIM/4 chunks (4 elems each)
#define K4F2   22            // F2DIM/4
#define FEATD  1019
#define MAXG   1024
#define MAXE   1000000
#define SCANB  1024
#define MAXNB  ((MAXN + SCANB - 1) / SCANB)

// ---------------- scratch (allocation-free rule: __device__ globals) ----------------
__device__ __align__(256) __half g_hA[MAXNP * F2DIM];   // 17.6 MB
__device__ __align__(256) __half g_hB[MAXNP * F2DIM];   // 17.6 MB
__device__ __align__(256) float g_dinv[MAXN];
__device__ __align__(256) int   g_indeg[MAXN];
__device__ __align__(256) int   g_cursor[MAXN];
__device__ __align__(256) int   g_off[MAXN + 1];
__device__ __align__(256) int2  g_epack[MAXE];          // (src, __float_as_int(norm))
__device__ __align__(256) int   g_partial[MAXNB + 1];
__device__ __align__(256) int   g_bofs[MAXNB + 1];
__device__ __align__(256) float g_pool[MAXG * FDIM];

// ---------------- f32x2 / half packing helpers ----------------
__device__ __forceinline__ unsigned long long ffma2(unsigned long long a,
                                                    unsigned long long b,
                                                    unsigned long long c) {
    unsigned long long d;
    asm("fma.rn.f32x2 %0, %1, %2, %3;" : "=l"(d) : "l"(a), "l"(b), "l"(c));
    return d;
}
__device__ __forceinline__ unsigned long long splat2(float x) {
    unsigned long long d;
    asm("mov.b64 %0, {%1, %2};" : "=l"(d) : "r"(__float_as_uint(x)), "r"(__float_as_uint(x)));
    return d;
}
__device__ __forceinline__ unsigned long long pack2(float lo, float hi) {
    unsigned long long d;
    asm("mov.b64 %0, {%1, %2};" : "=l"(d) : "r"(__float_as_uint(lo)), "r"(__float_as_uint(hi)));
    return d;
}
__device__ __forceinline__ float2 unpack2(unsigned long long v) {
    unsigned int lo, hi;
    asm("mov.b64 {%0, %1}, %2;" : "=r"(lo), "=r"(hi) : "l"(v));
    return make_float2(__uint_as_float(lo), __uint_as_float(hi));
}
__device__ __forceinline__ float4 h4tof4(uint2 u) {
    __half2 h0 = *reinterpret_cast<const __half2*>(&u.x);
    __half2 h1 = *reinterpret_cast<const __half2*>(&u.y);
    float2 f0 = __half22float2(h0);
    float2 f1 = __half22float2(h1);
    return make_float4(f0.x, f0.y, f1.x, f1.y);
}
__device__ __forceinline__ uint2 f4toh4(float x, float y, float z, float w) {
    __half2 p0 = __floats2half2_rn(x, y);
    __half2 p1 = __floats2half2_rn(z, w);
    uint2 u;
    u.x = *reinterpret_cast<unsigned int*>(&p0);
    u.y = *reinterpret_cast<unsigned int*>(&p1);
    return u;
}

// ---------------- degree count ----------------
__global__ void k_count(const int* __restrict__ dst, int* __restrict__ indeg, int E) {
    int e = blockIdx.x * blockDim.x + threadIdx.x;
    if (e < E) atomicAdd(&indeg[dst[e]], 1);
}

// ---------------- scan phase 1 (+ dinv + cursor zero fused) ----------------
__global__ void k_scan1(const int* __restrict__ indeg, int* __restrict__ off,
                        int* __restrict__ partial, float* __restrict__ dinv,
                        int* __restrict__ cursor, int n) {
    __shared__ int wsum[32];
    int tid = threadIdx.x, lane = tid & 31, wid = tid >> 5;
    int idx = blockIdx.x * SCANB + tid;
    int v = (idx < n) ? indeg[idx] : 0;
    if (idx < n) {
        dinv[idx] = rsqrtf(1.0f + (float)v);
        cursor[idx] = 0;
    }
    int incl = v;
    #pragma unroll
    for (int d = 1; d < 32; d <<= 1) {
        int t = __shfl_up_sync(0xffffffffu, incl, d);
        if (lane >= d) incl += t;
    }
    if (lane == 31) wsum[wid] = incl;
    __syncthreads();
    if (wid == 0) {
        int w = wsum[lane];
        #pragma unroll
        for (int d = 1; d < 32; d <<= 1) {
            int t = __shfl_up_sync(0xffffffffu, w, d);
            if (lane >= d) w += t;
        }
        wsum[lane] = w;
    }
    __syncthreads();
    int warpoff = (wid == 0) ? 0 : wsum[wid - 1];
    if (idx < n) off[idx] = warpoff + incl - v;
    if (tid == 0) partial[blockIdx.x] = wsum[31];
}

// ---------------- scan phase 2 (block offsets) ----------------
__global__ void k_scan2(const int* __restrict__ partial, int* __restrict__ bofs, int nb) {
    __shared__ int wsum[32];
    int tid = threadIdx.x, lane = tid & 31, wid = tid >> 5;  // 128 threads
    int v = (tid < nb) ? partial[tid] : 0;
    int incl = v;
    #pragma unroll
    for (int d = 1; d < 32; d <<= 1) {
        int t = __shfl_up_sync(0xffffffffu, incl, d);
        if (lane >= d) incl += t;
    }
    if (lane == 31) wsum[wid] = incl;
    __syncthreads();
    if (wid == 0 && lane < 4) {
        int w = wsum[lane];
        #pragma unroll
        for (int d = 1; d < 4; d <<= 1) {
            int t = __shfl_up_sync(0x0000000fu, w, d);
            if (lane >= d) w += t;
        }
        wsum[lane] = w;
    }
    __syncthreads();
    int warpoff = (wid == 0) ? 0 : wsum[wid - 1];
    if (tid < nb) bofs[tid] = warpoff + incl - v;
}

// ---------------- scan phase 3: finalize off (removes bofs from hot paths) ----------------
__global__ void k_scan3(int* __restrict__ off, const int* __restrict__ bofs, int n, int E) {
    int idx = blockIdx.x * blockDim.x + threadIdx.x;
    if (idx < n) off[idx] += bofs[idx >> 10];
    if (idx == 0) off[n] = E;
}

// ---------------- CSR fill (final offsets) ----------------
__global__ void k_fill(const int* __restrict__ src, const int* __restrict__ dst,
                       const float* __restrict__ dinv, const int* __restrict__ off,
                       int* __restrict__ cursor, int2* __restrict__ ep, int E) {
    int e = blockIdx.x * blockDim.x + threadIdx.x;
    if (e >= E) return;
    int s = src[e], d = dst[e];
    int p = off[d] + atomicAdd(&cursor[d], 1);
    ep[p] = make_int2(s, __float_as_int(dinv[s] * dinv[d]));
}

// ---------------- t = act(h) @ W (+bias) -> HALF output ----------------
// Register-blocked (fastest measured): 8 rows x one 4-col chunk per thread.
// HIN: 0 = fp32 input rows, 1 = fp16 input rows. Weights/bias fp32, accum fp32.
template <int HIN, int KIN, int KOUT4, int RELU, int BIAS>
__global__ void __launch_bounds__(256) k_mm(const void* __restrict__ hv,
                                            const float* __restrict__ W,
                                            const float* __restrict__ bias,
                                            __half* __restrict__ t, int n) {
    const int R = 8;
    int gid = blockIdx.x * 256 + threadIdx.x;
    int c4 = gid % KOUT4;
    int rb = gid / KOUT4;
    int row0 = rb * R;
    if (row0 >= n) return;

    const ulonglong2* Wv = (const ulonglong2*)W;
    unsigned long long binit0 = 0ull, binit1 = 0ull;
    if (BIAS) {
        float4 b4 = ((const float4*)bias)[c4];
        binit0 = pack2(b4.x, b4.y);
        binit1 = pack2(b4.z, b4.w);
    }
    unsigned long long acc0[R], acc1[R];
    #pragma unroll
    for (int r = 0; r < R; r++) { acc0[r] = binit0; acc1[r] = binit1; }

    const char* hp[R];
    #pragma unroll
    for (int r = 0; r < R; r++) {
        int rr = row0 + r; if (rr > n - 1) rr = n - 1;
        hp[r] = (const char*)hv + (size_t)rr * KIN * (HIN ? 2 : 4);
    }

    #pragma unroll 2
    for (int k4 = 0; k4 < KIN / 4; k4++) {
        float4 hvv[R];
        #pragma unroll
        for (int r = 0; r < R; r++) {
            float4 v;
            if (HIN) v = h4tof4(((const uint2*)hp[r])[k4]);
            else     v = ((const float4*)hp[r])[k4];
            if (RELU) {
                v.x = fmaxf(v.x, 0.f); v.y = fmaxf(v.y, 0.f);
                v.z = fmaxf(v.z, 0.f); v.w = fmaxf(v.w, 0.f);
            }
            hvv[r] = v;
        }
        #pragma unroll
        for (int kk = 0; kk < 4; kk++) {
            ulonglong2 wv = Wv[(k4 * 4 + kk) * KOUT4 + c4];
            #pragma unroll
            for (int r = 0; r < R; r++) {
                float hs = (kk == 0) ? hvv[r].x : (kk == 1) ? hvv[r].y
                         : (kk == 2) ? hvv[r].z : hvv[r].w;
                unsigned long long s = splat2(hs);
                acc0[r] = ffma2(s, wv.x, acc0[r]);
                acc1[r] = ffma2(s, wv.y, acc1[r]);
            }
        }
    }
    #pragma unroll
    for (int r = 0; r < R; r++) {
        int rr = row0 + r;
        if (rr < n) {
            float2 lo = unpack2(acc0[r]);
            float2 hi = unpack2(acc1[r]);
            ((uint2*)t)[(size_t)rr * KOUT4 + c4] = f4toh4(lo.x, lo.y, hi.x, hi.y);
        }
    }
}

// ---------------- F=44 HALF aggregation, thread = (node, 4-elem chunk) ----------------
// out[node] = [bias +] act(t[node])*dinv^2 + sum_{s in N(node)} act(t[s]) * norm
// t rows are 44 halfs (88B); chunk loads are uint2 (8B). Accumulate fp32, store half.
template <int RELU, int BIAS>
__global__ void __launch_bounds__(256) k_aggr(const __half* __restrict__ t,
                                              const int2* __restrict__ ep,
                                              const int* __restrict__ off,
                                              const float* __restrict__ dinv,
                                              const float* __restrict__ bias,
                                              __half* __restrict__ out, int n) {
    int gid = blockIdx.x * 256 + threadIdx.x;
    int node = gid / K4F;
    int c4 = gid - node * K4F;
    if (node >= n) return;

    const uint2* t4 = (const uint2*)t;
    float dd = dinv[node];
    float sl = dd * dd;

    float4 tv = h4tof4(t4[(size_t)node * K4F + c4]);
    if (RELU) {
        tv.x = fmaxf(tv.x, 0.f); tv.y = fmaxf(tv.y, 0.f);
        tv.z = fmaxf(tv.z, 0.f); tv.w = fmaxf(tv.w, 0.f);
    }
    float4 acc;
    if (BIAS) {
        float4 b4 = ((const float4*)bias)[c4];
        acc.x = fmaf(tv.x, sl, b4.x); acc.y = fmaf(tv.y, sl, b4.y);
        acc.z = fmaf(tv.z, sl, b4.z); acc.w = fmaf(tv.w, sl, b4.w);
    } else {
        acc.x = tv.x * sl; acc.y = tv.y * sl;
        acc.z = tv.z * sl; acc.w = tv.w * sl;
    }

    int j   = off[node];
    int end = off[node + 1];

    for (; j + 8 <= end; j += 8) {
        int2 m[8];
        #pragma unroll
        for (int q = 0; q < 8; q++) m[q] = ep[j + q];
        uint2 v[8];
        #pragma unroll
        for (int q = 0; q < 8; q++)
            v[q] = t4[(size_t)m[q].x * K4F + c4];
        #pragma unroll
        for (int q = 0; q < 8; q++) {
            float w = __int_as_float(m[q].y);
            float4 x = h4tof4(v[q]);
            if (RELU) {
                x.x = fmaxf(x.x, 0.f); x.y = fmaxf(x.y, 0.f);
                x.z = fmaxf(x.z, 0.f); x.w = fmaxf(x.w, 0.f);
            }
            acc.x = fmaf(x.x, w, acc.x); acc.y = fmaf(x.y, w, acc.y);
            acc.z = fmaf(x.z, w, acc.z); acc.w = fmaf(x.w, w, acc.w);
        }
    }
    if (j + 4 <= end) {
        int2 m[4];
        #pragma unroll
        for (int q = 0; q < 4; q++) m[q] = ep[j + q];
        uint2 v[4];
        #pragma unroll
        for (int q = 0; q < 4; q++)
            v[q] = t4[(size_t)m[q].x * K4F + c4];
        #pragma unroll
        for (int q = 0; q < 4; q++) {
            float w = __int_as_float(m[q].y);
            float4 x = h4tof4(v[q]);
            if (RELU) {
                x.x = fmaxf(x.x, 0.f); x.y = fmaxf(x.y, 0.f);
                x.z = fmaxf(x.z, 0.f); x.w = fmaxf(x.w, 0.f);
            }
            acc.x = fmaf(x.x, w, acc.x); acc.y = fmaf(x.y, w, acc.y);
            acc.z = fmaf(x.z, w, acc.z); acc.w = fmaf(x.w, w, acc.w);
        }
        j += 4;
    }
    for (; j < end; j++) {
        int2 m = ep[j];
        float w = __int_as_float(m.y);
        float4 x = h4tof4(t4[(size_t)m.x * K4F + c4]);
        if (RELU) {
            x.x = fmaxf(x.x, 0.f); x.y = fmaxf(x.y, 0.f);
            x.z = fmaxf(x.z, 0.f); x.w = fmaxf(x.w, 0.f);
        }
        acc.x = fmaf(x.x, w, acc.x); acc.y = fmaf(x.y, w, acc.y);
        acc.z = fmaf(x.z, w, acc.z); acc.w = fmaf(x.w, w, acc.w);
    }

    ((uint2*)out)[(size_t)node * K4F + c4] = f4toh4(acc.x, acc.y, acc.z, acc.w);
}

// ---------------- pooling over sorted batch (binary-searched segments, relu fused) -------
__device__ __forceinline__ int lowerb(const int* __restrict__ b, int n, int key) {
    int lo = 0, hi = n;
    while (lo < hi) {
        int mid = (lo + hi) >> 1;
        if (b[mid] < key) lo = mid + 1; else hi = mid;
    }
    return lo;
}
__global__ void k_pool(const __half* __restrict__ h, const int* __restrict__ batch,
                       float* __restrict__ pool, int n, int G) {
    int gid = blockIdx.x * blockDim.x + threadIdx.x;
    if (gid >= G * FDIM) return;
    int g = gid / FDIM;
    int j = gid - g * FDIM;
    int beg = lowerb(batch, n, g);
    int end = lowerb(batch, n, g + 1);
    float m0 = 0.f, m1 = 0.f, m2 = 0.f, m3 = 0.f;   // relu identity
    int i = beg;
    for (; i + 4 <= end; i += 4) {
        float a = __half2float(h[(size_t)(i + 0) * FDIM + j]);
        float b = __half2float(h[(size_t)(i + 1) * FDIM + j]);
        float c = __half2float(h[(size_t)(i + 2) * FDIM + j]);
        float d = __half2float(h[(size_t)(i + 3) * FDIM + j]);
        m0 = fmaxf(m0, a); m1 = fmaxf(m1, b);
        m2 = fmaxf(m2, c); m3 = fmaxf(m3, d);
    }
    for (; i < end; i++) m0 = fmaxf(m0, __half2float(h[(size_t)i * FDIM + j]));
    pool[g * FDIM + j] = fmaxf(fmaxf(m0, m1), fmaxf(m2, m3));
}

// ---------------- final heads: 8 graphs per block ----------------
__global__ void k_final(const float* __restrict__ pool, const float* __restrict__ feat,
                        const float* __restrict__ Wg,  const float* __restrict__ bg,
                        const float* __restrict__ Wf1, const float* __restrict__ bf1,
                        const float* __restrict__ Wf2, const float* __restrict__ bf2,
                        float* __restrict__ out, int G) {
    const int GB = 8;
    int g0 = blockIdx.x * GB;
    int j = threadIdx.x;   // 128
    float acc[GB];
    float bj = bf1[j];
    #pragma unroll
    for (int i = 0; i < GB; i++) acc[i] = bj;
    #pragma unroll 2
    for (int k = 0; k < FEATD; k++) {
        float w = Wf1[k * 128 + j];
        #pragma unroll
        for (int i = 0; i < GB; i++) {
            int g = g0 + i;
            float f = (g < G) ? feat[(size_t)g * FEATD + k] : 0.0f;
            acc[i] = fmaf(f, w, acc[i]);
        }
    }
    float wf2 = Wf2[j];
    __shared__ float red[128];
    __shared__ float sums[GB];
    #pragma unroll
    for (int i = 0; i < GB; i++) {
        red[j] = fmaxf(acc[i], 0.0f) * wf2;
        __syncthreads();
        for (int o = 64; o > 0; o >>= 1) {
            if (j < o) red[j] += red[j + o];
            __syncthreads();
        }
        if (j == 0) sums[i] = red[0];
        __syncthreads();
    }
    if (j < GB) {
        int g = g0 + j;
        if (g < G) {
            float a = bg[0];
            #pragma unroll
            for (int k = 0; k < FDIM; k++)
                a = fmaf(pool[g * FDIM + k], Wg[k], a);
            out[g] = fmaxf(a, 0.0f) + sums[j] + bf2[0];
        }
    }
}

// ----------------------------------------------------------------
extern "C" void kernel_launch(void* const* d_in, const int* in_sizes, int n_in,
                              void* d_out, int out_size) {
    const float* x       = (const float*)d_in[0];
    const int*   ei      = (const int*)  d_in[1];
    const int*   batch   = (const int*)  d_in[2];
    const float* feature = (const float*)d_in[3];
    const float* W1 = (const float*)d_in[4];  const float* b1 = (const float*)d_in[5];
    const float* W2 = (const float*)d_in[6];  const float* b2 = (const float*)d_in[7];
    const float* W3 = (const float*)d_in[8];  const float* b3 = (const float*)d_in[9];
    const float* Wg = (const float*)d_in[10]; const float* bg = (const float*)d_in[11];
    const float* Wf1= (const float*)d_in[12]; const float* bf1= (const float*)d_in[13];
    const float* Wf2= (const float*)d_in[14]; const float* bf2= (const float*)d_in[15];

    const int N = in_sizes[2];
    const int E = in_sizes[1] / 2;
    const int G = in_sizes[3] / FEATD;
    const int NB = (N + SCANB - 1) / SCANB;

    __half *A, *B;
    float *dinv, *pool;
    int *indeg, *cursor, *off, *partial, *bofs;
    int2 *ep;
    cudaGetSymbolAddress((void**)&A,      g_hA);
    cudaGetSymbolAddress((void**)&B,      g_hB);
    cudaGetSymbolAddress((void**)&dinv,   g_dinv);
    cudaGetSymbolAddress((void**)&indeg,  g_indeg);
    cudaGetSymbolAddress((void**)&cursor, g_cursor);
    cudaGetSymbolAddress((void**)&off,    g_off);
    cudaGetSymbolAddress((void**)&ep,     g_epack);
    cudaGetSymbolAddress((void**)&partial,g_partial);
    cudaGetSymbolAddress((void**)&bofs,   g_bofs);
    cudaGetSymbolAddress((void**)&pool,   g_pool);

    const int* src = ei;
    const int* dst = ei + E;
    float* out = (float*)d_out;

    const int T = 256;
    auto blocks = [&](int work) { return (work + T - 1) / T; };

    // ---- CSR build + norms ----
    cudaMemsetAsync(indeg, 0, N * sizeof(int));
    k_count<<<blocks(E), T>>>(dst, indeg, E);
    k_scan1<<<NB, SCANB>>>(indeg, off, partial, dinv, cursor, N);
    k_scan2<<<1, 128>>>(partial, bofs, NB);
    k_scan3<<<blocks(N), T>>>(off, bofs, N, E);

    // mm1 is CSR-independent: x(fp32, 44) @ W1 -> A(half, 44)
    {
        int thr = ((N + 7) / 8) * K4F;
        k_mm<0, FDIM, K4F, 0, 0><<<blocks(thr), T>>>(x, W1, nullptr, A, N);
    }
    k_fill<<<blocks(E), T>>>(src, dst, dinv, off, cursor, ep, E);

    // B = Agg(A)+b1 ; A = Agg(relu(B)) ; B88 = A@W2+b2 ; A = relu(B88)@W3 ; B = Agg(A)+b3
    k_aggr<0, 1><<<blocks(N * K4F), T>>>(A, ep, off, dinv, b1, B, N);
    k_aggr<1, 0><<<blocks(N * K4F), T>>>(B, ep, off, dinv, nullptr, A, N);
    {
        int thr = ((N + 7) / 8) * K4F2;
        k_mm<1, FDIM, K4F2, 0, 1><<<blocks(thr), T>>>(A, W2, b2, B, N);   // half in, 44->88
    }
    {
        int thr = ((N + 7) / 8) * K4F;
        k_mm<1, F2DIM, K4F, 1, 0><<<blocks(thr), T>>>(B, W3, nullptr, A, N);  // half in, relu, 88->44
    }
    k_aggr<0, 1><<<blocks(N * K4F), T>>>(A, ep, off, dinv, b3, B, N);

    // ---- pool + heads ----
    k_pool<<<blocks(G * FDIM), T>>>(B, batch, pool, N, G);
    k_final<<<(G + 7) / 8, 128>>>(pool, feature, Wg, bg, Wf1, bf1, Wf2, bf2, out, G);
}